// round 2
// baseline (speedup 1.0000x reference)
#include <cuda_runtime.h>

// Neural ODE (RK4, 100 steps) fused persistent kernel.
// B=4096 rows, D=H=256. dx/dt = tanh(x@W1+b1)@W2 + b2.
// Row-independent dynamics -> each CTA owns 32 rows for the entire
// integration; no cross-CTA sync, single kernel launch (1 graph node).
//
// Per-CTA per-GEMM: 32x256x256 FMA, W tiles (32x256) staged in smem,
// X/T1/H blocks resident in smem. Thread tile = 8 rows x 4 cols.
//
// NOTE: output is the flattened tuple (times[101], trajectory[101,4096,256]).
// traj therefore starts at byte offset 404 (NOT 16B aligned) -> all global
// trajectory stores are scalar float stores.

#define B_ROWS   4096
#define DIM      256
#define ROWS     32
#define NTHREADS 256
#define NSTEPS   100
#define KTILE    32
#define NCTAS    (B_ROWS / ROWS)   // 128

// smem layout (floats):
//   Xs  [32][256]   0     .. 8191
//   T1  [32][256]   8192  .. 16383
//   Hs  [32][256]   16384 .. 24575
//   Ws  [32][256]   24576 .. 32767   (W tile staging)
//   b1s [256]       32768 .. 33023
//   b2s [256]       33024 .. 33279
#define SMEM_FLOATS (4 * 8192 + 512)

extern __shared__ float smem[];

// Accumulate acc[r][c] += sum_k In[r0+r][k] * Wg[k][c0+c] over all 256 k.
// In: smem block [32][256]. Wg: global [256][256] row-major.
// Barrier discipline: syncthreads at top of each k-tile protects both the
// Ws reuse (previous GEMM's tile) and visibility of In writes.
__device__ __forceinline__ void gemm_acc(
    const float* __restrict__ In, const float* __restrict__ Wg,
    float* __restrict__ Ws, float acc[8][4],
    int r0, int c0, int tid)
{
    for (int kt = 0; kt < DIM / KTILE; kt++) {
        __syncthreads();
        // Cooperative load of W tile: 32x256 floats = 2048 float4, 8/thread.
        {
            const float4* src = reinterpret_cast<const float4*>(Wg + kt * KTILE * DIM);
            float4* dst = reinterpret_cast<float4*>(Ws);
            #pragma unroll
            for (int i = 0; i < 8; i++)
                dst[tid + i * NTHREADS] = src[tid + i * NTHREADS];
        }
        __syncthreads();

        const float* inb = In + r0 * DIM + kt * KTILE;
        #pragma unroll 8
        for (int k = 0; k < KTILE; k++) {
            // W row segment: lanes read contiguous 512B -> conflict-free LDS.128
            float4 w = *reinterpret_cast<const float4*>(Ws + k * DIM + c0);
            #pragma unroll
            for (int r = 0; r < 8; r++) {
                // all lanes in a warp share r0 -> broadcast LDS (no conflict)
                float xv = inb[r * DIM + k];
                acc[r][0] += xv * w.x;
                acc[r][1] += xv * w.y;
                acc[r][2] += xv * w.z;
                acc[r][3] += xv * w.w;
            }
        }
    }
}

// One vector-field eval: acc = tanh(In@W1+b1)@W2 + b2 for this thread's tile.
__device__ __forceinline__ void vf_eval(
    const float* __restrict__ In, float* __restrict__ Hs, float* __restrict__ Ws,
    const float* __restrict__ W1, const float* __restrict__ W2,
    const float* __restrict__ b1s, const float* __restrict__ b2s,
    float acc[8][4], int r0, int c0, int tid)
{
    #pragma unroll
    for (int r = 0; r < 8; r++) {
        acc[r][0] = b1s[c0 + 0];
        acc[r][1] = b1s[c0 + 1];
        acc[r][2] = b1s[c0 + 2];
        acc[r][3] = b1s[c0 + 3];
    }
    gemm_acc(In, W1, Ws, acc, r0, c0, tid);

    // tanh -> Hs (own tile; visibility to other threads guaranteed by the
    // syncthreads at the top of GEMM2's first k-tile)
    #pragma unroll
    for (int r = 0; r < 8; r++) {
        float4 h;
        h.x = tanhf(acc[r][0]);
        h.y = tanhf(acc[r][1]);
        h.z = tanhf(acc[r][2]);
        h.w = tanhf(acc[r][3]);
        *reinterpret_cast<float4*>(Hs + (r0 + r) * DIM + c0) = h;
        acc[r][0] = b2s[c0 + 0];
        acc[r][1] = b2s[c0 + 1];
        acc[r][2] = b2s[c0 + 2];
        acc[r][3] = b2s[c0 + 3];
    }
    gemm_acc(Hs, W2, Ws, acc, r0, c0, tid);
}

__global__ void __launch_bounds__(NTHREADS, 1)
ode_rk4_kernel(const float* __restrict__ x0, const float* __restrict__ tspan,
               const float* __restrict__ W1, const float* __restrict__ b1,
               const float* __restrict__ W2, const float* __restrict__ b2,
               float* __restrict__ times, float* __restrict__ traj)
{
    float* Xs  = smem;
    float* T1  = smem + 8192;
    float* Hs  = smem + 16384;
    float* Ws  = smem + 24576;
    float* b1s = smem + 32768;
    float* b2s = smem + 33024;

    const int tid = threadIdx.x;
    const int c0 = (tid & 63) * 4;          // column offset within 256
    const int r0 = (tid >> 6) * 8;          // row offset within 32
    const int row_base = blockIdx.x * ROWS;

    // Load biases into smem once.
    if (tid < 64)
        reinterpret_cast<float4*>(b1s)[tid] = reinterpret_cast<const float4*>(b1)[tid];
    else if (tid < 128)
        reinterpret_cast<float4*>(b2s)[tid - 64] = reinterpret_cast<const float4*>(b2)[tid - 64];

    // Load x0 block into Xs (x0 is a separate, aligned input buffer) and
    // emit trajectory frame 0 with scalar stores (traj may be 4B-aligned only).
    {
        const float4* src = reinterpret_cast<const float4*>(x0 + (long long)row_base * DIM);
        float* f0 = traj + (long long)row_base * DIM;
        float4* xs4 = reinterpret_cast<float4*>(Xs);
        #pragma unroll
        for (int i = 0; i < 8; i++) {
            float4 v = src[tid + i * NTHREADS];
            xs4[tid + i * NTHREADS] = v;
            int e = (tid + i * NTHREADS) * 4;
            f0[e + 0] = v.x;
            f0[e + 1] = v.y;
            f0[e + 2] = v.z;
            f0[e + 3] = v.w;
        }
    }

    // times vector (t0 + 0.01*i), one CTA handles it.
    if (times != nullptr && blockIdx.x == 0) {
        float t0 = tspan[0];
        for (int i = tid; i <= NSTEPS; i += NTHREADS)
            times[i] = t0 + 0.01f * (float)i;
    }

    const float half  = 0.005f;                   // dt/2
    const float dt    = 0.01f;
    const float sixth = (float)(0.01 / 6.0);      // dt/6, rounded like np.float32

    float kacc[8][4];
    float acc[8][4];

    const long long frame_stride = (long long)B_ROWS * DIM;

    for (int step = 0; step < NSTEPS; step++) {
        // ---- k1 = vf(x)
        vf_eval(Xs, Hs, Ws, W1, W2, b1s, b2s, acc, r0, c0, tid);
        #pragma unroll
        for (int r = 0; r < 8; r++) {
            float4 xv = *reinterpret_cast<const float4*>(Xs + (r0 + r) * DIM + c0);
            kacc[r][0] = acc[r][0]; kacc[r][1] = acc[r][1];
            kacc[r][2] = acc[r][2]; kacc[r][3] = acc[r][3];
            float4 t;
            t.x = xv.x + half * acc[r][0];
            t.y = xv.y + half * acc[r][1];
            t.z = xv.z + half * acc[r][2];
            t.w = xv.w + half * acc[r][3];
            *reinterpret_cast<float4*>(T1 + (r0 + r) * DIM + c0) = t;
        }

        // ---- k2 = vf(x + dt/2 * k1)
        vf_eval(T1, Hs, Ws, W1, W2, b1s, b2s, acc, r0, c0, tid);
        #pragma unroll
        for (int r = 0; r < 8; r++) {
            float4 xv = *reinterpret_cast<const float4*>(Xs + (r0 + r) * DIM + c0);
            kacc[r][0] += 2.0f * acc[r][0]; kacc[r][1] += 2.0f * acc[r][1];
            kacc[r][2] += 2.0f * acc[r][2]; kacc[r][3] += 2.0f * acc[r][3];
            float4 t;
            t.x = xv.x + half * acc[r][0];
            t.y = xv.y + half * acc[r][1];
            t.z = xv.z + half * acc[r][2];
            t.w = xv.w + half * acc[r][3];
            *reinterpret_cast<float4*>(T1 + (r0 + r) * DIM + c0) = t;
        }

        // ---- k3 = vf(x + dt/2 * k2)
        vf_eval(T1, Hs, Ws, W1, W2, b1s, b2s, acc, r0, c0, tid);
        #pragma unroll
        for (int r = 0; r < 8; r++) {
            float4 xv = *reinterpret_cast<const float4*>(Xs + (r0 + r) * DIM + c0);
            kacc[r][0] += 2.0f * acc[r][0]; kacc[r][1] += 2.0f * acc[r][1];
            kacc[r][2] += 2.0f * acc[r][2]; kacc[r][3] += 2.0f * acc[r][3];
            float4 t;
            t.x = xv.x + dt * acc[r][0];
            t.y = xv.y + dt * acc[r][1];
            t.z = xv.z + dt * acc[r][2];
            t.w = xv.w + dt * acc[r][3];
            *reinterpret_cast<float4*>(T1 + (r0 + r) * DIM + c0) = t;
        }

        // ---- k4 = vf(x + dt * k3); x += dt/6 * (k1 + 2k2 + 2k3 + k4)
        vf_eval(T1, Hs, Ws, W1, W2, b1s, b2s, acc, r0, c0, tid);
        float* fout = traj + (long long)(step + 1) * frame_stride
                           + (long long)row_base * DIM;
        #pragma unroll
        for (int r = 0; r < 8; r++) {
            float4 xv = *reinterpret_cast<const float4*>(Xs + (r0 + r) * DIM + c0);
            float4 nx;
            nx.x = xv.x + sixth * (kacc[r][0] + acc[r][0]);
            nx.y = xv.y + sixth * (kacc[r][1] + acc[r][1]);
            nx.z = xv.z + sixth * (kacc[r][2] + acc[r][2]);
            nx.w = xv.w + sixth * (kacc[r][3] + acc[r][3]);
            *reinterpret_cast<float4*>(Xs + (r0 + r) * DIM + c0) = nx;
            // scalar global stores: traj base is only 4B aligned
            float* fo = fout + (r0 + r) * DIM + c0;
            fo[0] = nx.x;
            fo[1] = nx.y;
            fo[2] = nx.z;
            fo[3] = nx.w;
        }
        // No trailing sync needed: Xs is only read cross-thread inside the
        // next vf_eval's GEMM1, whose first k-tile begins with __syncthreads.
    }
}

extern "C" void kernel_launch(void* const* d_in, const int* in_sizes, int n_in,
                              void* d_out, int out_size)
{
    const float* x0    = (const float*)d_in[0];
    const float* tspan = (const float*)d_in[1];
    const float* W1    = (const float*)d_in[2];
    const float* b1    = (const float*)d_in[3];
    const float* W2    = (const float*)d_in[4];
    const float* b2    = (const float*)d_in[5];

    float* out = (float*)d_out;
    const long long traj_elems = (long long)(NSTEPS + 1) * B_ROWS * DIM;

    // Output is the flattened tuple (times, trajectory). Fall back to
    // trajectory-only if out_size says so.
    float* times = nullptr;
    float* traj  = out;
    if ((long long)out_size >= traj_elems + (NSTEPS + 1)) {
        times = out;
        traj  = out + (NSTEPS + 1);
    }

    size_t smem_bytes = SMEM_FLOATS * sizeof(float);
    cudaFuncSetAttribute(ode_rk4_kernel,
                         cudaFuncAttributeMaxDynamicSharedMemorySize,
                         (int)smem_bytes);
    ode_rk4_kernel<<<NCTAS, NTHREADS, smem_bytes>>>(x0, tspan, W1, b1, W2, b2,
                                                    times, traj);
}

// round 4
// speedup vs baseline: 1.1745x; 1.1745x over previous
#include <cuda_runtime.h>

// Neural ODE (RK4, 100 steps) fused persistent kernel — round 3 (resubmit;
// R3 bench failed on infra before running).
// B=4096 rows, D=H=256. dx/dt = tanh(x@W1+b1)@W2 + b2.
// Each CTA owns 32 rows for the entire integration (row-independent ODE).
//
// This revision vs the 14.0ms baseline:
//  - k-vectorized inner loop: 12 LDS per 128 FMA (was 9 per 32)
//  - KTILE=64 W tiles, double-buffered via cp.async (L2 latency hidden)
//  - T1/H merged into one smem buffer (TH)
//
// Output tuple layout: (times[101], trajectory[101,4096,256]); traj starts at
// byte offset 404 -> all global trajectory stores are scalar.

#define B_ROWS   4096
#define DIM      256
#define ROWS     32
#define NTHREADS 256
#define NSTEPS   100
#define KTILE    64
#define NCTAS    (B_ROWS / ROWS)   // 128

// smem floats: Xs 8192 | TH 8192 | Ws 2*16384 | b1s 256 | b2s 256
#define XS_OFF   0
#define TH_OFF   8192
#define WS_OFF   16384
#define B1_OFF   (16384 + 32768)
#define B2_OFF   (B1_OFF + 256)
#define SMEM_FLOATS (B2_OFF + 256)

extern __shared__ float smem[];

// Async copy one 64x256 float W tile (64KB) into smem. One commit group.
__device__ __forceinline__ void cp_tile(float* dst, const float* __restrict__ src,
                                        int tid)
{
    unsigned ds = (unsigned)__cvta_generic_to_shared(dst);
    #pragma unroll
    for (int i = 0; i < 16; i++) {
        asm volatile("cp.async.cg.shared.global [%0], [%1], 16;\n"
                     :: "r"(ds + (unsigned)((tid + i * NTHREADS) * 16)),
                        "l"(src + (tid + i * NTHREADS) * 4));
    }
    asm volatile("cp.async.commit_group;\n" ::: "memory");
}

// acc[r][c] += sum over this 64-wide k tile of inb[r][k] * Wt[k][c0+c].
// inb = smem input row base (already offset by r0*DIM + koff).
__device__ __forceinline__ void mul_tile(const float* __restrict__ inb,
                                         const float* __restrict__ Wt,
                                         float acc[8][4], int c0)
{
    #pragma unroll 4
    for (int k4 = 0; k4 < KTILE / 4; k4++) {
        float4 xv[8];
        #pragma unroll
        for (int r = 0; r < 8; r++)   // broadcast LDS.128 (lanes share address)
            xv[r] = *reinterpret_cast<const float4*>(inb + r * DIM + k4 * 4);
        #pragma unroll
        for (int kk = 0; kk < 4; kk++) {
            // lanes read 512B contiguous -> conflict-free LDS.128
            float4 w = *reinterpret_cast<const float4*>(Wt + (k4 * 4 + kk) * DIM + c0);
            #pragma unroll
            for (int r = 0; r < 8; r++) {
                float x = (kk == 0) ? xv[r].x : (kk == 1) ? xv[r].y
                        : (kk == 2) ? xv[r].z : xv[r].w;
                acc[r][0] = fmaf(x, w.x, acc[r][0]);
                acc[r][1] = fmaf(x, w.y, acc[r][1]);
                acc[r][2] = fmaf(x, w.z, acc[r][2]);
                acc[r][3] = fmaf(x, w.w, acc[r][3]);
            }
        }
    }
}

// One vector-field eval: acc = tanh(In@W1+b1)@W2 + b2 for this thread's tile.
// 8 pipelined k-tiles (4 of W1, 4 of W2). On entry, Ws buf0 already holds
// W1 tile0 (prefetched by the previous vf's last iteration or by priming).
// On exit, buf0 holds the NEXT vf's W1 tile0.
__device__ __forceinline__ void vf_eval(
    const float* __restrict__ In,   // smem: Xs (k1) or TH (k2..k4 probe)
    float* __restrict__ TH, float* __restrict__ Ws,
    const float* __restrict__ W1, const float* __restrict__ W2,
    const float* __restrict__ b1s, const float* __restrict__ b2s,
    float acc[8][4], int r0, int c0, int tid)
{
    #pragma unroll
    for (int r = 0; r < 8; r++) {
        acc[r][0] = b1s[c0 + 0]; acc[r][1] = b1s[c0 + 1];
        acc[r][2] = b1s[c0 + 2]; acc[r][3] = b1s[c0 + 3];
    }
    #pragma unroll 1
    for (int t = 0; t < 8; t++) {
        // Prefetch next tile into the opposite buffer (chain continues into
        // the next vf's W1 tile0 at t==7; harmless at the very end).
        const float* nsrc = (t < 3) ? W1 + (t + 1) * KTILE * DIM
                          : (t < 7) ? W2 + (t - 3) * KTILE * DIM
                          : W1;
        cp_tile(Ws + ((t + 1) & 1) * (KTILE * DIM), nsrc, tid);
        asm volatile("cp.async.wait_group 1;\n" ::: "memory");
        __syncthreads();   // current tile resident; In/TH stores visible

        const float* inb = ((t < 4) ? In : TH) + r0 * DIM + (t & 3) * KTILE;
        mul_tile(inb, Ws + (t & 1) * (KTILE * DIM), acc, c0);
        __syncthreads();   // all threads done with this Ws buffer / In reads

        if (t == 3) {      // end of GEMM1: tanh -> TH, re-init acc with b2
            #pragma unroll
            for (int r = 0; r < 8; r++) {
                float4 h;
                h.x = tanhf(acc[r][0]); h.y = tanhf(acc[r][1]);
                h.z = tanhf(acc[r][2]); h.w = tanhf(acc[r][3]);
                *reinterpret_cast<float4*>(TH + (r0 + r) * DIM + c0) = h;
                acc[r][0] = b2s[c0 + 0]; acc[r][1] = b2s[c0 + 1];
                acc[r][2] = b2s[c0 + 2]; acc[r][3] = b2s[c0 + 3];
            }
        }
    }
}

__global__ void __launch_bounds__(NTHREADS, 1)
ode_rk4_kernel(const float* __restrict__ x0, const float* __restrict__ tspan,
               const float* __restrict__ W1, const float* __restrict__ b1,
               const float* __restrict__ W2, const float* __restrict__ b2,
               float* __restrict__ times, float* __restrict__ traj)
{
    float* Xs  = smem + XS_OFF;
    float* TH  = smem + TH_OFF;
    float* Ws  = smem + WS_OFF;
    float* b1s = smem + B1_OFF;
    float* b2s = smem + B2_OFF;

    const int tid = threadIdx.x;
    const int c0 = (tid & 63) * 4;          // column offset within 256
    const int r0 = (tid >> 6) * 8;          // row offset within 32
    const int row_base = blockIdx.x * ROWS;

    // Prime the cp.async pipeline: W1 tile0 -> buf0.
    cp_tile(Ws, W1, tid);

    // Biases into smem.
    if (tid < 64)
        reinterpret_cast<float4*>(b1s)[tid] = reinterpret_cast<const float4*>(b1)[tid];
    else if (tid < 128)
        reinterpret_cast<float4*>(b2s)[tid - 64] = reinterpret_cast<const float4*>(b2)[tid - 64];

    // x0 block -> Xs; trajectory frame 0 (scalar stores: traj 4B-aligned only).
    {
        const float4* src = reinterpret_cast<const float4*>(x0 + (long long)row_base * DIM);
        float* f0 = traj + (long long)row_base * DIM;
        float4* xs4 = reinterpret_cast<float4*>(Xs);
        #pragma unroll
        for (int i = 0; i < 8; i++) {
            float4 v = src[tid + i * NTHREADS];
            xs4[tid + i * NTHREADS] = v;
            int e = (tid + i * NTHREADS) * 4;
            f0[e + 0] = v.x; f0[e + 1] = v.y; f0[e + 2] = v.z; f0[e + 3] = v.w;
        }
    }

    // times vector (t0 + 0.01*i).
    if (times != nullptr && blockIdx.x == 0) {
        float t0 = tspan[0];
        for (int i = tid; i <= NSTEPS; i += NTHREADS)
            times[i] = t0 + 0.01f * (float)i;
    }

    const float half  = 0.005f;
    const float dt    = 0.01f;
    const float sixth = (float)(0.01 / 6.0);

    float kacc[8][4];
    float acc[8][4];
    const long long frame_stride = (long long)B_ROWS * DIM;

    for (int step = 0; step < NSTEPS; step++) {
        // ---- k1 = vf(x)
        vf_eval(Xs, TH, Ws, W1, W2, b1s, b2s, acc, r0, c0, tid);
        #pragma unroll
        for (int r = 0; r < 8; r++) {
            float4 xv = *reinterpret_cast<const float4*>(Xs + (r0 + r) * DIM + c0);
            kacc[r][0] = acc[r][0]; kacc[r][1] = acc[r][1];
            kacc[r][2] = acc[r][2]; kacc[r][3] = acc[r][3];
            float4 t;
            t.x = xv.x + half * acc[r][0];
            t.y = xv.y + half * acc[r][1];
            t.z = xv.z + half * acc[r][2];
            t.w = xv.w + half * acc[r][3];
            *reinterpret_cast<float4*>(TH + (r0 + r) * DIM + c0) = t;
        }

        // ---- k2 = vf(x + dt/2 * k1)
        vf_eval(TH, TH, Ws, W1, W2, b1s, b2s, acc, r0, c0, tid);
        #pragma unroll
        for (int r = 0; r < 8; r++) {
            float4 xv = *reinterpret_cast<const float4*>(Xs + (r0 + r) * DIM + c0);
            kacc[r][0] += 2.0f * acc[r][0]; kacc[r][1] += 2.0f * acc[r][1];
            kacc[r][2] += 2.0f * acc[r][2]; kacc[r][3] += 2.0f * acc[r][3];
            float4 t;
            t.x = xv.x + half * acc[r][0];
            t.y = xv.y + half * acc[r][1];
            t.z = xv.z + half * acc[r][2];
            t.w = xv.w + half * acc[r][3];
            *reinterpret_cast<float4*>(TH + (r0 + r) * DIM + c0) = t;
        }

        // ---- k3 = vf(x + dt/2 * k2)
        vf_eval(TH, TH, Ws, W1, W2, b1s, b2s, acc, r0, c0, tid);
        #pragma unroll
        for (int r = 0; r < 8; r++) {
            float4 xv = *reinterpret_cast<const float4*>(Xs + (r0 + r) * DIM + c0);
            kacc[r][0] += 2.0f * acc[r][0]; kacc[r][1] += 2.0f * acc[r][1];
            kacc[r][2] += 2.0f * acc[r][2]; kacc[r][3] += 2.0f * acc[r][3];
            float4 t;
            t.x = xv.x + dt * acc[r][0];
            t.y = xv.y + dt * acc[r][1];
            t.z = xv.z + dt * acc[r][2];
            t.w = xv.w + dt * acc[r][3];
            *reinterpret_cast<float4*>(TH + (r0 + r) * DIM + c0) = t;
        }

        // ---- k4 = vf(x + dt * k3); x += dt/6 * (k1 + 2k2 + 2k3 + k4)
        vf_eval(TH, TH, Ws, W1, W2, b1s, b2s, acc, r0, c0, tid);
        float* fout = traj + (long long)(step + 1) * frame_stride
                           + (long long)row_base * DIM;
        #pragma unroll
        for (int r = 0; r < 8; r++) {
            float4 xv = *reinterpret_cast<const float4*>(Xs + (r0 + r) * DIM + c0);
            float4 nx;
            nx.x = xv.x + sixth * (kacc[r][0] + acc[r][0]);
            nx.y = xv.y + sixth * (kacc[r][1] + acc[r][1]);
            nx.z = xv.z + sixth * (kacc[r][2] + acc[r][2]);
            nx.w = xv.w + sixth * (kacc[r][3] + acc[r][3]);
            *reinterpret_cast<float4*>(Xs + (r0 + r) * DIM + c0) = nx;
            float* fo = fout + (r0 + r) * DIM + c0;
            fo[0] = nx.x; fo[1] = nx.y; fo[2] = nx.z; fo[3] = nx.w;
        }
        // Next vf's tile0 sync orders these TH/Xs writes before any read.
    }
}

extern "C" void kernel_launch(void* const* d_in, const int* in_sizes, int n_in,
                              void* d_out, int out_size)
{
    const float* x0    = (const float*)d_in[0];
    const float* tspan = (const float*)d_in[1];
    const float* W1    = (const float*)d_in[2];
    const float* b1    = (const float*)d_in[3];
    const float* W2    = (const float*)d_in[4];
    const float* b2    = (const float*)d_in[5];

    float* out = (float*)d_out;
    const long long traj_elems = (long long)(NSTEPS + 1) * B_ROWS * DIM;

    float* times = nullptr;
    float* traj  = out;
    if ((long long)out_size >= traj_elems + (NSTEPS + 1)) {
        times = out;
        traj  = out + (NSTEPS + 1);
    }

    size_t smem_bytes = SMEM_FLOATS * sizeof(float);
    cudaFuncSetAttribute(ode_rk4_kernel,
                         cudaFuncAttributeMaxDynamicSharedMemorySize,
                         (int)smem_bytes);
    ode_rk4_kernel<<<NCTAS, NTHREADS, smem_bytes>>>(x0, tspan, W1, b1, W2, b2,
                                                    times, traj);
}

// round 5
// speedup vs baseline: 1.4015x; 1.1933x over previous
#include <cuda_runtime.h>

// Neural ODE (RK4, 100 steps) fused persistent kernel — round 5.
// B=4096 rows, D=H=256. dx/dt = tanh(x@W1+b1)@W2 + b2.
//
// vs 11.9ms version:
//  - inner product uses packed fma.rn.f32x2 (FFMA2): 2 FMAs per fma-pipe issue
//  - grid = 148 CTAs x 28 rows (all SMs busy; rows padded to 4144, pad rows
//    computed on clamped data and never stored)
//
// Output tuple layout: (times[101], trajectory[101,4096,256]); traj starts at
// byte offset 404 -> all global trajectory stores are scalar.

#define B_ROWS   4096
#define DIM      256
#define ROWS     28          // rows per CTA (padded coverage 148*28 = 4144)
#define NTHREADS 256
#define NSTEPS   100
#define KTILE    64
#define NCTAS    148
#define TR       7           // thread tile rows (ROWS / 4 row-groups)

// smem floats: Xs 7168 | TH 7168 | Ws 2*16384 | b1s 256 | b2s 256
#define XS_OFF   0
#define TH_OFF   (ROWS * DIM)
#define WS_OFF   (2 * ROWS * DIM)
#define B1_OFF   (WS_OFF + 2 * KTILE * DIM)
#define B2_OFF   (B1_OFF + 256)
#define SMEM_FLOATS (B2_OFF + 256)

extern __shared__ float smem[];

typedef unsigned long long u64;

__device__ __forceinline__ u64 pk2(float x) {           // (x, x) packed
    u64 v;
    asm("mov.b64 %0, {%1, %1};" : "=l"(v) : "f"(x));
    return v;
}
__device__ __forceinline__ float2 unpk(u64 v) {
    float2 f;
    asm("mov.b64 {%0, %1}, %2;" : "=f"(f.x), "=f"(f.y) : "l"(v));
    return f;
}
__device__ __forceinline__ void fma2(u64& d, u64 a, u64 b) {
    asm("fma.rn.f32x2 %0, %1, %2, %0;" : "+l"(d) : "l"(a), "l"(b));
}

// Async copy one 64x256 float W tile (64KB) into smem. One commit group.
__device__ __forceinline__ void cp_tile(float* dst, const float* __restrict__ src,
                                        int tid)
{
    unsigned ds = (unsigned)__cvta_generic_to_shared(dst);
    #pragma unroll
    for (int i = 0; i < 16; i++) {
        asm volatile("cp.async.cg.shared.global [%0], [%1], 16;\n"
                     :: "r"(ds + (unsigned)((tid + i * NTHREADS) * 16)),
                        "l"(src + (tid + i * NTHREADS) * 4));
    }
    asm volatile("cp.async.commit_group;\n" ::: "memory");
}

// acc2[r][p] += sum over this 64-wide k tile of inb[r][k] * Wt[k][c0+2p..+1].
// inb = smem input row base (already offset by r0*DIM + koff).
__device__ __forceinline__ void mul_tile(const float* __restrict__ inb,
                                         const float* __restrict__ Wt,
                                         u64 acc2[TR][2], int c0)
{
    #pragma unroll 2
    for (int k4 = 0; k4 < KTILE / 4; k4++) {
        float4 xv[TR];
        #pragma unroll
        for (int r = 0; r < TR; r++)   // broadcast LDS.128 (lanes share address)
            xv[r] = *reinterpret_cast<const float4*>(inb + r * DIM + k4 * 4);
        #pragma unroll
        for (int kk = 0; kk < 4; kk++) {
            // lanes read 512B contiguous -> conflict-free LDS.128
            ulonglong2 w = *reinterpret_cast<const ulonglong2*>(
                               Wt + (k4 * 4 + kk) * DIM + c0);
            #pragma unroll
            for (int r = 0; r < TR; r++) {
                float x = (kk == 0) ? xv[r].x : (kk == 1) ? xv[r].y
                        : (kk == 2) ? xv[r].z : xv[r].w;
                u64 xx = pk2(x);
                fma2(acc2[r][0], xx, w.x);
                fma2(acc2[r][1], xx, w.y);
            }
        }
    }
}

// One vector-field eval: accf = tanh(In@W1+b1)@W2 + b2 for this thread's tile.
// 8 pipelined k-tiles (4 of W1, 4 of W2). On entry, Ws buf0 already holds
// W1 tile0; on exit buf0 holds the next vf's W1 tile0 (cp.async chain).
__device__ __forceinline__ void vf_eval(
    const float* __restrict__ In,   // smem: Xs (k1) or TH (k2..k4 probe)
    float* __restrict__ TH, float* __restrict__ Ws,
    const float* __restrict__ W1, const float* __restrict__ W2,
    const float* __restrict__ b1s, const float* __restrict__ b2s,
    float accf[TR][4], int r0, int c0, int tid)
{
    u64 acc2[TR][2];
    {
        ulonglong2 b = *reinterpret_cast<const ulonglong2*>(b1s + c0);
        #pragma unroll
        for (int r = 0; r < TR; r++) { acc2[r][0] = b.x; acc2[r][1] = b.y; }
    }
    #pragma unroll 1
    for (int t = 0; t < 8; t++) {
        // Prefetch next tile into the opposite buffer (chain continues into
        // the next vf's W1 tile0 at t==7; harmless dead prefetch at the end).
        const float* nsrc = (t < 3) ? W1 + (t + 1) * KTILE * DIM
                          : (t < 7) ? W2 + (t - 3) * KTILE * DIM
                          : W1;
        cp_tile(Ws + ((t + 1) & 1) * (KTILE * DIM), nsrc, tid);
        asm volatile("cp.async.wait_group 1;\n" ::: "memory");
        __syncthreads();   // current tile resident; In/TH stores visible

        const float* inb = ((t < 4) ? In : TH) + r0 * DIM + (t & 3) * KTILE;
        mul_tile(inb, Ws + (t & 1) * (KTILE * DIM), acc2, c0);
        __syncthreads();   // all threads done with this Ws buffer / In reads

        if (t == 3) {      // end of GEMM1: tanh -> TH, re-init acc with b2
            ulonglong2 b = *reinterpret_cast<const ulonglong2*>(b2s + c0);
            #pragma unroll
            for (int r = 0; r < TR; r++) {
                float2 a0 = unpk(acc2[r][0]);
                float2 a1 = unpk(acc2[r][1]);
                float4 h;
                h.x = tanhf(a0.x); h.y = tanhf(a0.y);
                h.z = tanhf(a1.x); h.w = tanhf(a1.y);
                *reinterpret_cast<float4*>(TH + (r0 + r) * DIM + c0) = h;
                acc2[r][0] = b.x; acc2[r][1] = b.y;
            }
        }
    }
    #pragma unroll
    for (int r = 0; r < TR; r++) {
        float2 a0 = unpk(acc2[r][0]);
        float2 a1 = unpk(acc2[r][1]);
        accf[r][0] = a0.x; accf[r][1] = a0.y;
        accf[r][2] = a1.x; accf[r][3] = a1.y;
    }
}

__global__ void __launch_bounds__(NTHREADS, 1)
ode_rk4_kernel(const float* __restrict__ x0, const float* __restrict__ tspan,
               const float* __restrict__ W1, const float* __restrict__ b1,
               const float* __restrict__ W2, const float* __restrict__ b2,
               float* __restrict__ times, float* __restrict__ traj)
{
    float* Xs  = smem + XS_OFF;
    float* TH  = smem + TH_OFF;
    float* Ws  = smem + WS_OFF;
    float* b1s = smem + B1_OFF;
    float* b2s = smem + B2_OFF;

    const int tid = threadIdx.x;
    const int c0 = (tid & 63) * 4;          // column offset within 256
    const int r0 = (tid >> 6) * TR;         // row offset within 28
    const int row_base = blockIdx.x * ROWS; // may exceed 4096-28 (padded)

    // Prime the cp.async pipeline: W1 tile0 -> buf0.
    cp_tile(Ws, W1, tid);

    // Biases into smem.
    if (tid < 64)
        reinterpret_cast<float4*>(b1s)[tid] = reinterpret_cast<const float4*>(b1)[tid];
    else if (tid < 128)
        reinterpret_cast<float4*>(b2s)[tid - 64] = reinterpret_cast<const float4*>(b2)[tid - 64];

    // x0 block -> Xs (rows clamped to 4095 for pad rows); trajectory frame 0
    // (scalar stores, guarded; traj base only 4B-aligned).
    {
        float* f0 = traj + (long long)row_base * DIM;
        float4* xs4 = reinterpret_cast<float4*>(Xs);
        #pragma unroll
        for (int i = 0; i < TR; i++) {
            int p = tid + i * NTHREADS;              // 0 .. 1791 (28*64)
            int lrow = p >> 6;                       // local row 0..27
            int grow = row_base + lrow;
            int crow = (grow < B_ROWS) ? grow : (B_ROWS - 1);
            float4 v = *reinterpret_cast<const float4*>(
                           x0 + (long long)crow * DIM + (p & 63) * 4);
            xs4[p] = v;
            if (grow < B_ROWS) {
                float* fo = f0 + lrow * DIM + (p & 63) * 4;
                fo[0] = v.x; fo[1] = v.y; fo[2] = v.z; fo[3] = v.w;
            }
        }
    }

    // times vector (t0 + 0.01*i).
    if (times != nullptr && blockIdx.x == 0) {
        float t0 = tspan[0];
        for (int i = tid; i <= NSTEPS; i += NTHREADS)
            times[i] = t0 + 0.01f * (float)i;
    }

    const float half  = 0.005f;
    const float dt    = 0.01f;
    const float sixth = (float)(0.01 / 6.0);

    float kacc[TR][4];
    float acc[TR][4];
    const long long frame_stride = (long long)B_ROWS * DIM;

    for (int step = 0; step < NSTEPS; step++) {
        // ---- k1 = vf(x)
        vf_eval(Xs, TH, Ws, W1, W2, b1s, b2s, acc, r0, c0, tid);
        #pragma unroll
        for (int r = 0; r < TR; r++) {
            float4 xv = *reinterpret_cast<const float4*>(Xs + (r0 + r) * DIM + c0);
            kacc[r][0] = acc[r][0]; kacc[r][1] = acc[r][1];
            kacc[r][2] = acc[r][2]; kacc[r][3] = acc[r][3];
            float4 t;
            t.x = xv.x + half * acc[r][0];
            t.y = xv.y + half * acc[r][1];
            t.z = xv.z + half * acc[r][2];
            t.w = xv.w + half * acc[r][3];
            *reinterpret_cast<float4*>(TH + (r0 + r) * DIM + c0) = t;
        }

        // ---- k2 = vf(x + dt/2 * k1)
        vf_eval(TH, TH, Ws, W1, W2, b1s, b2s, acc, r0, c0, tid);
        #pragma unroll
        for (int r = 0; r < TR; r++) {
            float4 xv = *reinterpret_cast<const float4*>(Xs + (r0 + r) * DIM + c0);
            kacc[r][0] += 2.0f * acc[r][0]; kacc[r][1] += 2.0f * acc[r][1];
            kacc[r][2] += 2.0f * acc[r][2]; kacc[r][3] += 2.0f * acc[r][3];
            float4 t;
            t.x = xv.x + half * acc[r][0];
            t.y = xv.y + half * acc[r][1];
            t.z = xv.z + half * acc[r][2];
            t.w = xv.w + half * acc[r][3];
            *reinterpret_cast<float4*>(TH + (r0 + r) * DIM + c0) = t;
        }

        // ---- k3 = vf(x + dt/2 * k2)
        vf_eval(TH, TH, Ws, W1, W2, b1s, b2s, acc, r0, c0, tid);
        #pragma unroll
        for (int r = 0; r < TR; r++) {
            float4 xv = *reinterpret_cast<const float4*>(Xs + (r0 + r) * DIM + c0);
            kacc[r][0] += 2.0f * acc[r][0]; kacc[r][1] += 2.0f * acc[r][1];
            kacc[r][2] += 2.0f * acc[r][2]; kacc[r][3] += 2.0f * acc[r][3];
            float4 t;
            t.x = xv.x + dt * acc[r][0];
            t.y = xv.y + dt * acc[r][1];
            t.z = xv.z + dt * acc[r][2];
            t.w = xv.w + dt * acc[r][3];
            *reinterpret_cast<float4*>(TH + (r0 + r) * DIM + c0) = t;
        }

        // ---- k4 = vf(x + dt * k3); x += dt/6 * (k1 + 2k2 + 2k3 + k4)
        vf_eval(TH, TH, Ws, W1, W2, b1s, b2s, acc, r0, c0, tid);
        float* fout = traj + (long long)(step + 1) * frame_stride
                           + (long long)row_base * DIM;
        #pragma unroll
        for (int r = 0; r < TR; r++) {
            float4 xv = *reinterpret_cast<const float4*>(Xs + (r0 + r) * DIM + c0);
            float4 nx;
            nx.x = xv.x + sixth * (kacc[r][0] + acc[r][0]);
            nx.y = xv.y + sixth * (kacc[r][1] + acc[r][1]);
            nx.z = xv.z + sixth * (kacc[r][2] + acc[r][2]);
            nx.w = xv.w + sixth * (kacc[r][3] + acc[r][3]);
            *reinterpret_cast<float4*>(Xs + (r0 + r) * DIM + c0) = nx;
            if (row_base + r0 + r < B_ROWS) {   // skip pad rows
                float* fo = fout + (r0 + r) * DIM + c0;
                fo[0] = nx.x; fo[1] = nx.y; fo[2] = nx.z; fo[3] = nx.w;
            }
        }
        // Next vf's tile0 sync orders these TH/Xs writes before any read.
    }
}

extern "C" void kernel_launch(void* const* d_in, const int* in_sizes, int n_in,
                              void* d_out, int out_size)
{
    const float* x0    = (const float*)d_in[0];
    const float* tspan = (const float*)d_in[1];
    const float* W1    = (const float*)d_in[2];
    const float* b1    = (const float*)d_in[3];
    const float* W2    = (const float*)d_in[4];
    const float* b2    = (const float*)d_in[5];

    float* out = (float*)d_out;
    const long long traj_elems = (long long)(NSTEPS + 1) * B_ROWS * DIM;

    float* times = nullptr;
    float* traj  = out;
    if ((long long)out_size >= traj_elems + (NSTEPS + 1)) {
        times = out;
        traj  = out + (NSTEPS + 1);
    }

    size_t smem_bytes = SMEM_FLOATS * sizeof(float);
    cudaFuncSetAttribute(ode_rk4_kernel,
                         cudaFuncAttributeMaxDynamicSharedMemorySize,
                         (int)smem_bytes);
    ode_rk4_kernel<<<NCTAS, NTHREADS, smem_bytes>>>(x0, tspan, W1, b1, W2, b2,
                                                    times, traj);
}

// round 8
// speedup vs baseline: 2.7757x; 1.9805x over previous
#include <cuda_runtime.h>
#include <cuda_bf16.h>
#include <cstdint>

// Neural ODE RK4 on tensor cores via mma.sync (sm_100-safe; tcgen05 is
// rejected by this toolchain's compute_100 PTX target).
// B=4096, D=H=256, 100 RK4 steps. dx/dt = tanh(x@W1+b1)@W2 + b2.
// GEMMs in bf16 hi/lo split: D = Ah*Bh + Ah*Bl + Al*Bh (fp32 accum).
//
// 128 persistent CTAs x 32 rows. 8 warps/CTA; warp w owns the M32 x
// N[w*32..w*32+32) output slab -> C, x, kacc all live in registers in the
// m16n8 fragment layout. A (x / tanh) kept as bf16 hi/lo tiles in smem
// (528B-padded rows, conflict-free ldmatrix). W pre-split + padded by a
// repack kernel, streamed as double-buffered k64-chunks via cp.async.
//
// R7 fix: A tile k-offset now advances with the W chunk ((t&3)*128 bytes);
// previously every chunk re-read A[:, 0:64] -> rel_err 0.47.
//
// Output = flattened tuple (times[101], traj[101,4096,256]); traj starts at
// byte offset 404 -> scalar 4B global stores for trajectory.

#define NSTEPS   100
#define BROWS    4096
#define DIM      256
#define MROWS    32
#define NCTAS    128
#define NTHREADS 256

#define ASTRIDE  528                 // bytes per padded 256-bf16 row
#define PART_EL  16896               // 64 * 264 bf16 elements per k64 part
#define PARTB    (64 * ASTRIDE)      // 33792 B
#define CHUNKB   (2 * PARTB)         // hi+lo, 67584 B
#define A_HI     0
#define A_LO     16896               // bytes: 32 rows * 528
#define W_OFF    33792
#define SMEM_BYTES (W_OFF + 2 * CHUNKB)   // 168960

__device__ __align__(16) __nv_bfloat16 g_Wp[2 * 4 * 2 * PART_EL]; // [mat][chunk][part]

// ---------------- helpers ----------------
__device__ __forceinline__ uint32_t smem_u32(const void* p) {
    uint32_t a;
    asm("{ .reg .u64 t; cvta.to.shared.u64 t, %1; cvt.u32.u64 %0, t; }"
        : "=r"(a) : "l"(p));
    return a;
}
__device__ __forceinline__ void ldsm_x4(uint32_t r[4], uint32_t a) {
    asm volatile("ldmatrix.sync.aligned.m8n8.x4.shared.b16 {%0,%1,%2,%3}, [%4];"
                 : "=r"(r[0]), "=r"(r[1]), "=r"(r[2]), "=r"(r[3]) : "r"(a));
}
__device__ __forceinline__ void ldsm_x2t(uint32_t r[2], uint32_t a) {
    asm volatile("ldmatrix.sync.aligned.m8n8.x2.trans.shared.b16 {%0,%1}, [%2];"
                 : "=r"(r[0]), "=r"(r[1]) : "r"(a));
}
__device__ __forceinline__ void mma16816(float c[4], const uint32_t a[4],
                                         const uint32_t b[2]) {
    asm volatile("mma.sync.aligned.m16n8k16.row.col.f32.bf16.bf16.f32 "
                 "{%0,%1,%2,%3}, {%4,%5,%6,%7}, {%8,%9}, {%0,%1,%2,%3};"
                 : "+f"(c[0]), "+f"(c[1]), "+f"(c[2]), "+f"(c[3])
                 : "r"(a[0]), "r"(a[1]), "r"(a[2]), "r"(a[3]),
                   "r"(b[0]), "r"(b[1]));
}
// split (va, vb) into bf16 hi/lo pairs and store into A tiles
__device__ __forceinline__ void splitstore(uint32_t ahi, uint32_t alo,
                                           float va, float vb) {
    __nv_bfloat162 h = __floats2bfloat162_rn(va, vb);
    float2 hf = __bfloat1622float2(h);
    __nv_bfloat162 l = __floats2bfloat162_rn(va - hf.x, vb - hf.y);
    uint32_t hu = *reinterpret_cast<uint32_t*>(&h);
    uint32_t lu = *reinterpret_cast<uint32_t*>(&l);
    asm volatile("st.shared.b32 [%0], %1;" :: "r"(ahi), "r"(hu) : "memory");
    asm volatile("st.shared.b32 [%0], %1;" :: "r"(alo), "r"(lu) : "memory");
}

// ---------------- repack: W[k][n] fp32 -> hi/lo bf16, padded rows ----------
__global__ void repack_kernel(const float* __restrict__ W1,
                              const float* __restrict__ W2)
{
    int t = blockIdx.x * blockDim.x + threadIdx.x;
    if (t >= 2 * DIM * DIM) return;
    int mat = t >> 16;
    int k   = (t >> 8) & 255;
    int n   = t & 255;
    float w = (mat ? W2 : W1)[k * DIM + n];
    __nv_bfloat16 h = __float2bfloat16(w);
    __nv_bfloat16 l = __float2bfloat16(w - __bfloat162float(h));
    int chunk = k >> 6;
    int idx = (mat * 4 + chunk) * 2 * PART_EL + (k & 63) * 264 + n;
    g_Wp[idx]           = h;
    g_Wp[idx + PART_EL] = l;
}

// ---------------- main kernel ----------------
extern __shared__ char smem_raw[];

__device__ __forceinline__ void cp_chunk(int mat, int c, int buf,
                                         uint32_t sb, int tid)
{
    uint32_t dst = sb + W_OFF + (uint32_t)buf * CHUNKB;
    const char* src = reinterpret_cast<const char*>(g_Wp)
                    + (size_t)(mat * 4 + c) * CHUNKB;
    for (int i = tid; i < CHUNKB / 16; i += NTHREADS) {
        asm volatile("cp.async.cg.shared.global [%0], [%1], 16;\n"
                     :: "r"(dst + (uint32_t)i * 16u), "l"(src + (size_t)i * 16));
    }
    asm volatile("cp.async.commit_group;\n" ::: "memory");
}

// one k64 chunk of the M32 x N32 (per-warp) GEMM, 3-term bf16 split.
// akoff = byte offset of this chunk's k64 slice within the A row (kchunk*128).
__device__ __forceinline__ void compute_chunk(float c[2][4][4], uint32_t sb,
                                              int buf, uint32_t aoff,
                                              uint32_t akoff, uint32_t boff)
{
    uint32_t wb = sb + W_OFF + (uint32_t)buf * CHUNKB;
    #pragma unroll
    for (int ks = 0; ks < 4; ks++) {
        uint32_t ab = sb + A_HI + aoff + akoff + (uint32_t)ks * 32u;
        uint32_t ah[2][4], al[2][4];
        ldsm_x4(ah[0], ab);
        ldsm_x4(ah[1], ab + 16u * ASTRIDE);
        ldsm_x4(al[0], ab + (A_LO - A_HI));
        ldsm_x4(al[1], ab + (A_LO - A_HI) + 16u * ASTRIDE);

        uint32_t bb = wb + boff + (uint32_t)ks * 16u * ASTRIDE;
        uint32_t bh[4][2], bl[4][2];
        #pragma unroll
        for (int nt = 0; nt < 4; nt++) {
            ldsm_x2t(bh[nt], bb + (uint32_t)nt * 16u);
            ldsm_x2t(bl[nt], bb + PARTB + (uint32_t)nt * 16u);
        }
        #pragma unroll
        for (int mt = 0; mt < 2; mt++)
            #pragma unroll
            for (int nt = 0; nt < 4; nt++) {
                mma16816(c[mt][nt], ah[mt], bh[nt]);
                mma16816(c[mt][nt], ah[mt], bl[nt]);
                mma16816(c[mt][nt], al[mt], bh[nt]);
            }
    }
}

__global__ void __launch_bounds__(NTHREADS, 1)
ode_tc_kernel(const float* __restrict__ x0, const float* __restrict__ tspan,
              const float* __restrict__ b1, const float* __restrict__ b2,
              float* __restrict__ times, float* __restrict__ traj)
{
    uint32_t sb = smem_u32(smem_raw);
    const int tid  = threadIdx.x;
    const int lane = tid & 31;
    const int w    = tid >> 5;
    const int r0   = lane >> 2;
    const int cp2  = (lane & 3) * 2;
    const int row_base = blockIdx.x * MROWS;

    // ldmatrix per-thread byte offsets
    const uint32_t aoff = (uint32_t)(((lane & 7) + ((lane >> 3) & 1) * 8) * ASTRIDE
                                     + (lane >> 4) * 16);
    const uint32_t boff = (uint32_t)((lane & 15) * ASTRIDE + w * 64);

    // prime the cp.async pipeline: mat0 chunk0 -> buf0
    cp_chunk(0, 0, 0, sb, tid);

    // biases for this thread's fixed columns
    float b1v[4][2], b2v[4][2];
    #pragma unroll
    for (int nt = 0; nt < 4; nt++) {
        int col = w * 32 + nt * 8 + cp2;
        b1v[nt][0] = b1[col];     b1v[nt][1] = b1[col + 1];
        b2v[nt][0] = b2[col];     b2v[nt][1] = b2[col + 1];
    }

    float c[2][4][4], xv[2][4][4], kc[2][4][4];

    // init: x0 -> registers + A tiles (hi/lo) + trajectory frame 0
    #pragma unroll
    for (int mt = 0; mt < 2; mt++)
        #pragma unroll
        for (int nt = 0; nt < 4; nt++) {
            int col = w * 32 + nt * 8 + cp2;
            #pragma unroll
            for (int rh = 0; rh < 2; rh++) {
                int row = mt * 16 + r0 + rh * 8;
                long long g = (long long)(row_base + row) * DIM + col;
                float v0 = x0[g], v1 = x0[g + 1];
                xv[mt][nt][rh * 2]     = v0;
                xv[mt][nt][rh * 2 + 1] = v1;
                traj[g] = v0; traj[g + 1] = v1;
                uint32_t ao = sb + (uint32_t)(row * ASTRIDE + col * 2);
                splitstore(ao + A_HI, ao + A_LO, v0, v1);
            }
            #pragma unroll
            for (int e = 0; e < 4; e++) c[mt][nt][e] = b1v[nt][e & 1];
        }

    if (times != nullptr && blockIdx.x == 0) {
        float t0 = tspan[0];
        for (int i = tid; i <= NSTEPS; i += NTHREADS)
            times[i] = t0 + 0.01f * (float)i;
    }

    const float halfdt = 0.005f;
    const float dt     = 0.01f;
    const float sixth  = (float)(0.01 / 6.0);
    const long long frame = (long long)BROWS * DIM;

    #pragma unroll 1
    for (int step = 0; step < NSTEPS; step++) {
        #pragma unroll 1
        for (int s = 0; s < 4; s++) {
            // -------- one vf eval: 8 k64 chunks (4 x W1, 4 x W2) --------
            #pragma unroll 1
            for (int t = 0; t < 8; t++) {
                int imat = (t < 3) ? 0 : (t < 7) ? 1 : 0;
                int ic   = (t < 3) ? t + 1 : (t < 7) ? t - 3 : 0;
                cp_chunk(imat, ic, (t + 1) & 1, sb, tid);
                asm volatile("cp.async.wait_group 1;\n" ::: "memory");
                __syncthreads();                 // chunk resident, A visible
                compute_chunk(c, sb, t & 1, aoff,
                              (uint32_t)(t & 3) * 128u, boff);
                __syncthreads();                 // done with buf + A reads

                if (t == 3) {                    // epi1: h = tanh(D) -> A
                    #pragma unroll
                    for (int mt = 0; mt < 2; mt++)
                        #pragma unroll
                        for (int nt = 0; nt < 4; nt++) {
                            int col = w * 32 + nt * 8 + cp2;
                            #pragma unroll
                            for (int rh = 0; rh < 2; rh++) {
                                int row = mt * 16 + r0 + rh * 8;
                                float v0 = tanhf(c[mt][nt][rh * 2]);
                                float v1 = tanhf(c[mt][nt][rh * 2 + 1]);
                                uint32_t ao = sb + (uint32_t)(row * ASTRIDE + col * 2);
                                splitstore(ao + A_HI, ao + A_LO, v0, v1);
                            }
                            #pragma unroll
                            for (int e = 0; e < 4; e++)
                                c[mt][nt][e] = b2v[nt][e & 1];
                        }
                }
            }

            // -------- epi2: k ready in c; RK4 combine; next A --------
            #pragma unroll
            for (int mt = 0; mt < 2; mt++)
                #pragma unroll
                for (int nt = 0; nt < 4; nt++) {
                    int col = w * 32 + nt * 8 + cp2;
                    #pragma unroll
                    for (int rh = 0; rh < 2; rh++) {
                        int row = mt * 16 + r0 + rh * 8;
                        float v[2];
                        #pragma unroll
                        for (int j = 0; j < 2; j++) {
                            int e = rh * 2 + j;
                            float k = c[mt][nt][e];
                            float x = xv[mt][nt][e];
                            if (s == 0) {
                                kc[mt][nt][e] = k;
                                v[j] = x + halfdt * k;
                            } else if (s == 1) {
                                kc[mt][nt][e] += 2.0f * k;
                                v[j] = x + halfdt * k;
                            } else if (s == 2) {
                                kc[mt][nt][e] += 2.0f * k;
                                v[j] = x + dt * k;
                            } else {
                                float xn = x + sixth * (kc[mt][nt][e] + k);
                                xv[mt][nt][e] = xn;
                                v[j] = xn;
                            }
                        }
                        uint32_t ao = sb + (uint32_t)(row * ASTRIDE + col * 2);
                        splitstore(ao + A_HI, ao + A_LO, v[0], v[1]);
                        if (s == 3) {
                            long long g = (long long)(step + 1) * frame
                                        + (long long)(row_base + row) * DIM + col;
                            traj[g]     = v[0];
                            traj[g + 1] = v[1];
                        }
                    }
                    #pragma unroll
                    for (int e = 0; e < 4; e++)
                        c[mt][nt][e] = b1v[nt][e & 1];
                }
            // next chunk's pre-compute __syncthreads orders these A writes
        }
    }
}

extern "C" void kernel_launch(void* const* d_in, const int* in_sizes, int n_in,
                              void* d_out, int out_size)
{
    const float* x0    = (const float*)d_in[0];
    const float* tspan = (const float*)d_in[1];
    const float* W1    = (const float*)d_in[2];
    const float* b1    = (const float*)d_in[3];
    const float* W2    = (const float*)d_in[4];
    const float* b2    = (const float*)d_in[5];

    float* out = (float*)d_out;
    const long long traj_elems = (long long)(NSTEPS + 1) * BROWS * DIM;
    float* times = nullptr;
    float* traj  = out;
    if ((long long)out_size >= traj_elems + (NSTEPS + 1)) {
        times = out;
        traj  = out + (NSTEPS + 1);
    }

    repack_kernel<<<512, 256>>>(W1, W2);

    cudaFuncSetAttribute(ode_tc_kernel,
                         cudaFuncAttributeMaxDynamicSharedMemorySize, SMEM_BYTES);
    ode_tc_kernel<<<NCTAS, NTHREADS, SMEM_BYTES>>>(x0, tspan, b1, b2, times, traj);
}